// round 1
// baseline (speedup 1.0000x reference)
#include <cuda_runtime.h>

#define D 1024
#define MAX_B 32
#define CHUNK 8
#define EPS 1e-6f

__device__ float g_decay[D];
__device__ float g_state[MAX_B * D];
__device__ float g_pool[MAX_B * D];
__device__ float g_maxdecay;

__device__ __forceinline__ float warp_sum(float v) {
#pragma unroll
    for (int o = 16; o > 0; o >>= 1) v += __shfl_xor_sync(0xffffffffu, v, o);
    return v;
}

// ---------------- Kernel 1: decay = sigmoid(logit), max(decay), zero state ----
__global__ void prep_kernel(const float* __restrict__ logit, int B) {
    int tid = threadIdx.x;  // 1024 threads
    float dcy = 1.f / (1.f + expf(-logit[tid]));
    g_decay[tid] = dcy;
    for (int b = 0; b < B; b++) g_state[b * D + tid] = 0.f;

    __shared__ float sm[32];
    float m = dcy;
#pragma unroll
    for (int o = 16; o > 0; o >>= 1) m = fmaxf(m, __shfl_xor_sync(0xffffffffu, m, o));
    if ((tid & 31) == 0) sm[tid >> 5] = m;
    __syncthreads();
    if (tid < 32) {
        float v = sm[tid];
#pragma unroll
        for (int o = 16; o > 0; o >>= 1) v = fmaxf(v, __shfl_xor_sync(0xffffffffu, v, o));
        if (tid == 0) g_maxdecay = v;
    }
}

// ---------------- Kernel 2: truncated decay-weighted scan with fused rmsnorm ----
// Block = one (batch, 8-timestep chunk). Blocks whose max possible weight is
// < 1e-12 exit before touching x. Active blocks:
//   load 8 rows (float4/thread, MLP=8) -> per-row sum-of-squares block reduce
//   -> rstd -> acc_d += decay_d^{S-1-t} * x * rstd -> atomicAdd into g_state.
__global__ void scan_kernel(const float* __restrict__ x,
                            const float* __restrict__ norm1_w, int S) {
    const int b = blockIdx.y;
    const int chunk = blockIdx.x;
    const int t_lo = chunk * CHUNK;
    int t_hi = t_lo + (CHUNK - 1);
    if (t_hi > S - 1) t_hi = S - 1;
    const int e_min = (S - 1) - t_hi;           // exponent of newest row in chunk
    const int valid = t_hi - t_lo + 1;          // rows actually in-range (<= 8)

    if (e_min > 0 && __powf(g_maxdecay, (float)e_min) < 1e-12f) return;

    const int tid = threadIdx.x;                // 256 threads
    const int d0 = tid * 4;
    const float4 dc4 = *(const float4*)&g_decay[d0];

    const float* xb = x + ((size_t)b * S + t_hi) * D + d0;
    float4 xr[CHUNK];
#pragma unroll
    for (int i = 0; i < CHUNK; i++) {
        if (i < valid) xr[i] = *(const float4*)(xb - (size_t)i * D);
        else           xr[i] = make_float4(0.f, 0.f, 0.f, 0.f);
    }

    float ssq[CHUNK];
#pragma unroll
    for (int i = 0; i < CHUNK; i++) {
        float4 v = xr[i];
        float s = v.x * v.x + v.y * v.y + v.z * v.z + v.w * v.w;
        ssq[i] = warp_sum(s);
    }

    __shared__ float sred[CHUNK][8];
    __shared__ float srstd[CHUNK];
    const int wid = tid >> 5, lane = tid & 31;
    if (lane == 0) {
#pragma unroll
        for (int i = 0; i < CHUNK; i++) sred[i][wid] = ssq[i];
    }
    __syncthreads();
    if (tid < CHUNK) {
        float s = 0.f;
#pragma unroll
        for (int w = 0; w < 8; w++) s += sred[tid][w];
        srstd[tid] = rsqrtf(s * (1.f / D) + EPS);
    }
    __syncthreads();

    // geometric weights: row i (t = t_hi - i) has weight decay^(e_min + i)
    float4 w4;
    w4.x = __powf(dc4.x, (float)e_min);
    w4.y = __powf(dc4.y, (float)e_min);
    w4.z = __powf(dc4.z, (float)e_min);
    w4.w = __powf(dc4.w, (float)e_min);

    float4 acc = make_float4(0.f, 0.f, 0.f, 0.f);
#pragma unroll
    for (int i = 0; i < CHUNK; i++) {
        if (i < valid) {
            float r = srstd[i];
            acc.x += w4.x * xr[i].x * r;
            acc.y += w4.y * xr[i].y * r;
            acc.z += w4.z * xr[i].z * r;
            acc.w += w4.w * xr[i].w * r;
        }
        w4.x *= dc4.x; w4.y *= dc4.y; w4.z *= dc4.z; w4.w *= dc4.w;
    }

    const float4 nw = *(const float4*)&norm1_w[d0];
    float* gs = &g_state[b * D + d0];
    atomicAdd(gs + 0, acc.x * nw.x * (1.f - dc4.x));
    atomicAdd(gs + 1, acc.y * nw.y * (1.f - dc4.y));
    atomicAdd(gs + 2, acc.z * nw.z * (1.f - dc4.z));
    atomicAdd(gs + 3, acc.w * nw.w * (1.f - dc4.w));
}

// ---------------- Kernel 3: pool = rmsnorm(x[:,S-1,:] + state, norm2_w) ------
__global__ void pool_kernel(const float* __restrict__ x,
                            const float* __restrict__ norm2_w, int S) {
    const int b = blockIdx.x;
    const int tid = threadIdx.x;   // 256
    const int d0 = tid * 4;

    const float4 xl = *(const float4*)(x + ((size_t)b * S + (S - 1)) * D + d0);
    const float4 st = *(const float4*)&g_state[b * D + d0];
    float4 v = make_float4(xl.x + st.x, xl.y + st.y, xl.z + st.z, xl.w + st.w);

    float s = v.x * v.x + v.y * v.y + v.z * v.z + v.w * v.w;
    s = warp_sum(s);
    __shared__ float sm[8];
    __shared__ float srs;
    if ((tid & 31) == 0) sm[tid >> 5] = s;
    __syncthreads();
    if (tid == 0) {
        float t = 0.f;
#pragma unroll
        for (int w = 0; w < 8; w++) t += sm[w];
        srs = rsqrtf(t * (1.f / D) + EPS);
    }
    __syncthreads();

    const float r = srs;
    const float4 nw = *(const float4*)&norm2_w[d0];
    float4 p = make_float4(v.x * r * nw.x, v.y * r * nw.y,
                           v.z * r * nw.z, v.w * r * nw.w);
    *(float4*)&g_pool[b * D + d0] = p;
}

// ---------------- Kernel 4: expert-grouped GEMV + ReLU ------------------------
// Block = (expert e, tile of 8 output rows). Each W[e] row is loaded once and
// dotted against every pool vector whose batch selected expert e.
__global__ void gemm_kernel(const int* __restrict__ experts,
                            const float* __restrict__ W,
                            float* __restrict__ out, int B) {
    const int e = blockIdx.y;
    const int otile = blockIdx.x;

    __shared__ int s_nb;
    __shared__ int s_bl[MAX_B];
    if (threadIdx.x == 0) {
        int n = 0;
        for (int b = 0; b < B && n < 16; b++)
            if (experts[b] == e) s_bl[n++] = b;
        s_nb = n;
    }
    __syncthreads();
    const int nb = s_nb;
    if (nb == 0) return;

    const int wid = threadIdx.x >> 5, lane = threadIdx.x & 31;
    const int o = otile * 8 + wid;
    const float* Wr = W + ((size_t)e * D + o) * D;

    float acc[16];
#pragma unroll
    for (int j = 0; j < 16; j++) acc[j] = 0.f;

#pragma unroll
    for (int i = 0; i < 8; i++) {
        const int dd = i * 128 + lane * 4;
        const float4 w4 = *(const float4*)(Wr + dd);
#pragma unroll
        for (int j = 0; j < 16; j++) {
            if (j < nb) {
                const float4 p4 = *(const float4*)&g_pool[s_bl[j] * D + dd];
                acc[j] += w4.x * p4.x + w4.y * p4.y + w4.z * p4.z + w4.w * p4.w;
            }
        }
    }

#pragma unroll
    for (int j = 0; j < 16; j++) {
        if (j < nb) {
            float s = warp_sum(acc[j]);
            if (lane == 0) out[s_bl[j] * D + o] = fmaxf(s, 0.f);
        }
    }
}

// ---------------- Launch -------------------------------------------------------
extern "C" void kernel_launch(void* const* d_in, const int* in_sizes, int n_in,
                              void* d_out, int out_size) {
    const float* x        = (const float*)d_in[0];
    const int*   experts  = (const int*)d_in[1];
    const float* norm1_w  = (const float*)d_in[2];
    const float* tdl      = (const float*)d_in[3];
    const float* norm2_w  = (const float*)d_in[4];
    const float* W        = (const float*)d_in[5];
    float* out = (float*)d_out;

    const int B = in_sizes[1];
    const int S = in_sizes[0] / (B * D);
    const int E = in_sizes[5] / (D * D);

    prep_kernel<<<1, 1024>>>(tdl, B);

    dim3 gscan((S + CHUNK - 1) / CHUNK, B);
    scan_kernel<<<gscan, 256>>>(x, norm1_w, S);

    pool_kernel<<<B, 256>>>(x, norm2_w, S);

    dim3 ggemm(D / 8, E);
    gemm_kernel<<<ggemm, 256>>>(experts, W, out, B);
}

// round 2
// speedup vs baseline: 1.3119x; 1.3119x over previous
#include <cuda_runtime.h>

#define D 1024
#define MAX_B 32
#define MAX_E 8
#define CHUNK 8
#define GRP 4
#define EPS 1e-6f

__device__ float g_decay[D];
__device__ float g_state[MAX_B * D];
__device__ float g_pool[MAX_B * D];
__device__ float g_maxdecay;
__device__ int   g_cnt[MAX_E];
__device__ int   g_bl[MAX_E][MAX_B];

__device__ __forceinline__ float warp_sum(float v) {
#pragma unroll
    for (int o = 16; o > 0; o >>= 1) v += __shfl_xor_sync(0xffffffffu, v, o);
    return v;
}

// ---- Kernel 1: sigmoid(decay), max(decay), zero state, group batches by expert ----
__global__ void prep_kernel(const float* __restrict__ logit,
                            const int* __restrict__ experts, int B, int E) {
    int tid = threadIdx.x;  // 1024 threads
    float dcy = 1.f / (1.f + expf(-logit[tid]));
    g_decay[tid] = dcy;
    for (int b = 0; b < B; b++) g_state[b * D + tid] = 0.f;

    __shared__ float sm[32];
    float m = dcy;
#pragma unroll
    for (int o = 16; o > 0; o >>= 1) m = fmaxf(m, __shfl_xor_sync(0xffffffffu, m, o));
    if ((tid & 31) == 0) sm[tid >> 5] = m;
    __syncthreads();
    if (tid < 32) {
        float v = sm[tid];
#pragma unroll
        for (int o = 16; o > 0; o >>= 1) v = fmaxf(v, __shfl_xor_sync(0xffffffffu, v, o));
        if (tid == 0) g_maxdecay = v;
    }
    // expert grouping (serial, tiny)
    if (tid == 0) {
        for (int e = 0; e < E; e++) {
            int n = 0;
            for (int b = 0; b < B; b++)
                if (experts[b] == e) g_bl[e][n++] = b;
            g_cnt[e] = n;
        }
    }
}

// ---- Kernel 2: truncated decay-weighted scan, fused rmsnorm, atomic accumulate ----
__global__ void scan_kernel(const float* __restrict__ x,
                            const float* __restrict__ norm1_w, int S) {
    const int b = blockIdx.y;
    const int chunk = blockIdx.x;
    const int t_lo = chunk * CHUNK;
    int t_hi = t_lo + (CHUNK - 1);
    if (t_hi > S - 1) t_hi = S - 1;
    const int e_min = (S - 1) - t_hi;
    const int valid = t_hi - t_lo + 1;

    if (e_min > 0 && __powf(g_maxdecay, (float)e_min) < 1e-12f) return;

    const int tid = threadIdx.x;   // 256
    const int d0 = tid * 4;
    const float4 dc4 = *(const float4*)&g_decay[d0];

    const float* xb = x + ((size_t)b * S + t_hi) * D + d0;
    float4 xr[CHUNK];
#pragma unroll
    for (int i = 0; i < CHUNK; i++) {
        if (i < valid) xr[i] = *(const float4*)(xb - (size_t)i * D);
        else           xr[i] = make_float4(0.f, 0.f, 0.f, 0.f);
    }

    float ssq[CHUNK];
#pragma unroll
    for (int i = 0; i < CHUNK; i++) {
        float4 v = xr[i];
        ssq[i] = warp_sum(v.x * v.x + v.y * v.y + v.z * v.z + v.w * v.w);
    }

    __shared__ float sred[CHUNK][8];
    __shared__ float srstd[CHUNK];
    const int wid = tid >> 5, lane = tid & 31;
    if (lane == 0) {
#pragma unroll
        for (int i = 0; i < CHUNK; i++) sred[i][wid] = ssq[i];
    }
    __syncthreads();
    if (tid < CHUNK) {
        float s = 0.f;
#pragma unroll
        for (int w = 0; w < 8; w++) s += sred[tid][w];
        srstd[tid] = rsqrtf(s * (1.f / D) + EPS);
    }
    __syncthreads();

    float4 w4;
    w4.x = __powf(dc4.x, (float)e_min);
    w4.y = __powf(dc4.y, (float)e_min);
    w4.z = __powf(dc4.z, (float)e_min);
    w4.w = __powf(dc4.w, (float)e_min);

    float4 acc = make_float4(0.f, 0.f, 0.f, 0.f);
#pragma unroll
    for (int i = 0; i < CHUNK; i++) {
        if (i < valid) {
            float r = srstd[i];
            acc.x += w4.x * xr[i].x * r;
            acc.y += w4.y * xr[i].y * r;
            acc.z += w4.z * xr[i].z * r;
            acc.w += w4.w * xr[i].w * r;
        }
        w4.x *= dc4.x; w4.y *= dc4.y; w4.z *= dc4.z; w4.w *= dc4.w;
    }

    const float4 nw = *(const float4*)&norm1_w[d0];
    float* gs = &g_state[b * D + d0];
    atomicAdd(gs + 0, acc.x * nw.x * (1.f - dc4.x));
    atomicAdd(gs + 1, acc.y * nw.y * (1.f - dc4.y));
    atomicAdd(gs + 2, acc.z * nw.z * (1.f - dc4.z));
    atomicAdd(gs + 3, acc.w * nw.w * (1.f - dc4.w));
}

// ---- Kernel 3: pool = rmsnorm(x[:,S-1,:] + state, norm2_w) ----
__global__ void pool_kernel(const float* __restrict__ x,
                            const float* __restrict__ norm2_w, int S) {
    const int b = blockIdx.x;
    const int tid = threadIdx.x;   // 256
    const int d0 = tid * 4;

    const float4 xl = *(const float4*)(x + ((size_t)b * S + (S - 1)) * D + d0);
    const float4 st = *(const float4*)&g_state[b * D + d0];
    float4 v = make_float4(xl.x + st.x, xl.y + st.y, xl.z + st.z, xl.w + st.w);

    float s = warp_sum(v.x * v.x + v.y * v.y + v.z * v.z + v.w * v.w);
    __shared__ float sm[8];
    __shared__ float srs;
    if ((tid & 31) == 0) sm[tid >> 5] = s;
    __syncthreads();
    if (tid == 0) {
        float t = 0.f;
#pragma unroll
        for (int w = 0; w < 8; w++) t += sm[w];
        srs = rsqrtf(t * (1.f / D) + EPS);
    }
    __syncthreads();

    const float r = srs;
    const float4 nw = *(const float4*)&norm2_w[d0];
    float4 p = make_float4(v.x * r * nw.x, v.y * r * nw.y,
                           v.z * r * nw.z, v.w * r * nw.w);
    *(float4*)&g_pool[b * D + d0] = p;
}

// ---- Kernel 4: expert-grouped GEMV, groups of 4 batches, pool in shared ----
// block = (row-tile of 8, expert e, batch-group g). Each warp: one output row.
// W row: 8 independent LDG.128 per lane upfront; pool: 4 rows staged in smem.
__global__ void gemm_kernel(const float* __restrict__ W,
                            float* __restrict__ out) {
    const int e = blockIdx.y;
    const int g = blockIdx.z;
    const int nb = g_cnt[e];
    const int base = g * GRP;
    if (base >= nb) return;
    const int cnt = min(GRP, nb - base);

    __shared__ float s_pool[GRP][D];
    const int tid = threadIdx.x;   // 256
#pragma unroll
    for (int j = 0; j < GRP; j++) {
        float4 p = make_float4(0.f, 0.f, 0.f, 0.f);
        if (j < cnt) p = *(const float4*)&g_pool[g_bl[e][base + j] * D + tid * 4];
        *(float4*)&s_pool[j][tid * 4] = p;
    }
    __syncthreads();

    const int warp = tid >> 5, lane = tid & 31;
    const int o = blockIdx.x * 8 + warp;
    const float* Wr = W + ((size_t)e * D + o) * D;

    float4 w[8];
#pragma unroll
    for (int i = 0; i < 8; i++)
        w[i] = *(const float4*)(Wr + i * 128 + lane * 4);

    float acc[GRP] = {0.f, 0.f, 0.f, 0.f};
#pragma unroll
    for (int i = 0; i < 8; i++) {
#pragma unroll
        for (int j = 0; j < GRP; j++) {
            const float4 p = *(const float4*)&s_pool[j][i * 128 + lane * 4];
            acc[j] += w[i].x * p.x + w[i].y * p.y + w[i].z * p.z + w[i].w * p.w;
        }
    }

#pragma unroll
    for (int j = 0; j < GRP; j++) {
        float s = warp_sum(acc[j]);
        if (lane == 0 && j < cnt)
            out[g_bl[e][base + j] * D + o] = fmaxf(s, 0.f);
    }
}

// ---- Launch ----
extern "C" void kernel_launch(void* const* d_in, const int* in_sizes, int n_in,
                              void* d_out, int out_size) {
    const float* x        = (const float*)d_in[0];
    const int*   experts  = (const int*)d_in[1];
    const float* norm1_w  = (const float*)d_in[2];
    const float* tdl      = (const float*)d_in[3];
    const float* norm2_w  = (const float*)d_in[4];
    const float* W        = (const float*)d_in[5];
    float* out = (float*)d_out;

    const int B = in_sizes[1];
    const int S = in_sizes[0] / (B * D);
    const int E = in_sizes[5] / (D * D);

    prep_kernel<<<1, 1024>>>(tdl, experts, B, E);

    dim3 gscan((S + CHUNK - 1) / CHUNK, B);
    scan_kernel<<<gscan, 256>>>(x, norm1_w, S);

    pool_kernel<<<B, 256>>>(x, norm2_w, S);

    dim3 ggemm(D / 8, E, (B + GRP - 1) / GRP);
    gemm_kernel<<<ggemm, 256>>>(W, out);
}

// round 3
// speedup vs baseline: 1.5838x; 1.2073x over previous
#include <cuda_runtime.h>

#define D 1024
#define MAX_B 32
#define MAX_E 8
#define CHUNK 8
#define GRP 4
#define NBX 32
#define EPS 1e-6f

__device__ float g_decay[D];
__device__ float g_state[MAX_B * D];
__device__ float g_pool[MAX_B * D];
__device__ float g_maxdecay;
__device__ int   g_nchunks;
__device__ int   g_arrive[MAX_B];
__device__ int   g_cnt[MAX_E];
__device__ int   g_bl[MAX_E][MAX_B];

__device__ __forceinline__ float warp_sum(float v) {
#pragma unroll
    for (int o = 16; o > 0; o >>= 1) v += __shfl_xor_sync(0xffffffffu, v, o);
    return v;
}

// ---- Kernel 1: sigmoid, max(decay) -> nchunks, zero state/counters, expert groups ----
__global__ void prep_kernel(const float* __restrict__ logit,
                            const int* __restrict__ experts, int B, int E, int S) {
    int tid = threadIdx.x;  // 1024
    float dcy = 1.f / (1.f + expf(-logit[tid]));
    g_decay[tid] = dcy;
    for (int b = 0; b < B; b++) g_state[b * D + tid] = 0.f;
    if (tid < MAX_B) g_arrive[tid] = 0;

    __shared__ float sm[32];
    float m = dcy;
#pragma unroll
    for (int o = 16; o > 0; o >>= 1) m = fmaxf(m, __shfl_xor_sync(0xffffffffu, m, o));
    if ((tid & 31) == 0) sm[tid >> 5] = m;
    __syncthreads();
    if (tid < 32) {
        float v = sm[tid];
#pragma unroll
        for (int o = 16; o > 0; o >>= 1) v = fmaxf(v, __shfl_xor_sync(0xffffffffu, v, o));
        if (tid == 0) {
            g_maxdecay = v;
            int sch = (S + CHUNK - 1) / CHUNK;
            int nch;
            if (v >= 0.9999995f) {
                nch = sch;
            } else {
                float K = logf(1e-12f) / logf(v);   // maxd^K = 1e-12
                int Ki = (int)K + 2;
                nch = (Ki + CHUNK - 1) / CHUNK;
                if (nch > sch) nch = sch;
                if (nch < 1) nch = 1;
            }
            g_nchunks = nch;
        }
    }
    if (tid == 0) {
        for (int e = 0; e < E; e++) {
            int n = 0;
            for (int b = 0; b < B; b++)
                if (experts[b] == e) g_bl[e][n++] = b;
            g_cnt[e] = n;
        }
    }
}

// ---- Kernel 2: truncated scan (strided chunks, no empty blocks) + fused pool ----
__global__ void scan_kernel(const float* __restrict__ x,
                            const float* __restrict__ norm1_w,
                            const float* __restrict__ norm2_w, int S) {
    const int b = blockIdx.y;
    const int tid = threadIdx.x;    // 256
    const int d0 = tid * 4;
    const int wid = tid >> 5, lane = tid & 31;
    const int nch = g_nchunks;

    const float4 dc4 = *(const float4*)&g_decay[d0];
    float4 acc = make_float4(0.f, 0.f, 0.f, 0.f);

    __shared__ float sred[CHUNK][8];
    __shared__ float srstd[CHUNK];

    for (int c = blockIdx.x; c < nch; c += NBX) {
        const int t_hi = S - 1 - c * CHUNK;
        int t_lo = t_hi - (CHUNK - 1);
        if (t_lo < 0) t_lo = 0;
        const int valid = t_hi - t_lo + 1;
        const int e_min = c * CHUNK;

        const float* xb = x + ((size_t)b * S + t_hi) * D + d0;
        float4 xr[CHUNK];
#pragma unroll
        for (int i = 0; i < CHUNK; i++) {
            if (i < valid) xr[i] = *(const float4*)(xb - (size_t)i * D);
            else           xr[i] = make_float4(0.f, 0.f, 0.f, 0.f);
        }

#pragma unroll
        for (int i = 0; i < CHUNK; i++) {
            float4 v = xr[i];
            float s = warp_sum(v.x * v.x + v.y * v.y + v.z * v.z + v.w * v.w);
            if (lane == 0) sred[i][wid] = s;
        }
        __syncthreads();
        if (tid < CHUNK) {
            float s = 0.f;
#pragma unroll
            for (int w = 0; w < 8; w++) s += sred[tid][w];
            srstd[tid] = rsqrtf(s * (1.f / D) + EPS);
        }
        __syncthreads();

        float4 w4;
        w4.x = __powf(dc4.x, (float)e_min);
        w4.y = __powf(dc4.y, (float)e_min);
        w4.z = __powf(dc4.z, (float)e_min);
        w4.w = __powf(dc4.w, (float)e_min);

#pragma unroll
        for (int i = 0; i < CHUNK; i++) {
            if (i < valid) {
                float r = srstd[i];
                acc.x += w4.x * xr[i].x * r;
                acc.y += w4.y * xr[i].y * r;
                acc.z += w4.z * xr[i].z * r;
                acc.w += w4.w * xr[i].w * r;
            }
            w4.x *= dc4.x; w4.y *= dc4.y; w4.z *= dc4.z; w4.w *= dc4.w;
        }
        __syncthreads();   // protect sred reuse next iteration
    }

    const float4 nw = *(const float4*)&norm1_w[d0];
    float* gs = &g_state[b * D + d0];
    atomicAdd(gs + 0, acc.x * nw.x * (1.f - dc4.x));
    atomicAdd(gs + 1, acc.y * nw.y * (1.f - dc4.y));
    atomicAdd(gs + 2, acc.z * nw.z * (1.f - dc4.z));
    atomicAdd(gs + 3, acc.w * nw.w * (1.f - dc4.w));

    // ---- last block per batch computes pool = rmsnorm(x[b,S-1]+state, norm2_w) ----
    __threadfence();
    __shared__ int s_last;
    if (tid == 0)
        s_last = (atomicAdd(&g_arrive[b], 1) == NBX - 1);
    __syncthreads();
    if (!s_last) return;

    const float4 xl = *(const float4*)(x + ((size_t)b * S + (S - 1)) * D + d0);
    const float4 st = __ldcg((const float4*)&g_state[b * D + d0]);
    float4 v = make_float4(xl.x + st.x, xl.y + st.y, xl.z + st.z, xl.w + st.w);

    float s = warp_sum(v.x * v.x + v.y * v.y + v.z * v.z + v.w * v.w);
    __shared__ float sm2[8];
    __shared__ float srs;
    if (lane == 0) sm2[wid] = s;
    __syncthreads();
    if (tid == 0) {
        float t = 0.f;
#pragma unroll
        for (int w = 0; w < 8; w++) t += sm2[w];
        srs = rsqrtf(t * (1.f / D) + EPS);
    }
    __syncthreads();

    const float r = srs;
    const float4 n2 = *(const float4*)&norm2_w[d0];
    float4 p = make_float4(v.x * r * n2.x, v.y * r * n2.y,
                           v.z * r * n2.z, v.w * r * n2.w);
    *(float4*)&g_pool[b * D + d0] = p;
}

// ---- Kernel 3: expert-grouped GEMV, 2 rows/warp, pool-register reuse ----
__global__ void gemm_kernel(const float* __restrict__ W,
                            float* __restrict__ out) {
    const int e = blockIdx.y;
    const int g = blockIdx.z;
    const int nb = g_cnt[e];
    const int base = g * GRP;
    if (base >= nb) return;
    const int cnt = min(GRP, nb - base);

    __shared__ float s_pool[GRP][D];   // 16 KB
    const int tid = threadIdx.x;       // 256
#pragma unroll
    for (int j = 0; j < GRP; j++) {
        float4 p = make_float4(0.f, 0.f, 0.f, 0.f);
        if (j < cnt) p = *(const float4*)&g_pool[g_bl[e][base + j] * D + tid * 4];
        *(float4*)&s_pool[j][tid * 4] = p;
    }
    __syncthreads();

    const int warp = tid >> 5, lane = tid & 31;
    const int row0 = blockIdx.x * 16 + warp * 2;     // 2 rows per warp
    const float* W0 = W + ((size_t)e * D + row0) * D;
    const float* W1 = W0 + D;

    float acc0[GRP] = {0.f, 0.f, 0.f, 0.f};
    float acc1[GRP] = {0.f, 0.f, 0.f, 0.f};

    float4 a0 = __ldg((const float4*)(W0 + lane * 4));
    float4 a1 = __ldg((const float4*)(W1 + lane * 4));

#pragma unroll
    for (int i = 0; i < 8; i++) {
        float4 n0, n1;
        if (i < 7) {
            n0 = __ldg((const float4*)(W0 + (i + 1) * 128 + lane * 4));
            n1 = __ldg((const float4*)(W1 + (i + 1) * 128 + lane * 4));
        }
#pragma unroll
        for (int j = 0; j < GRP; j++) {
            const float4 p = *(const float4*)&s_pool[j][i * 128 + lane * 4];
            acc0[j] += a0.x * p.x + a0.y * p.y + a0.z * p.z + a0.w * p.w;
            acc1[j] += a1.x * p.x + a1.y * p.y + a1.z * p.z + a1.w * p.w;
        }
        if (i < 7) { a0 = n0; a1 = n1; }
    }

#pragma unroll
    for (int j = 0; j < GRP; j++) {
        float s0 = warp_sum(acc0[j]);
        float s1 = warp_sum(acc1[j]);
        if (lane == 0 && j < cnt) {
            const int ob = g_bl[e][base + j] * D;
            out[ob + row0]     = fmaxf(s0, 0.f);
            out[ob + row0 + 1] = fmaxf(s1, 0.f);
        }
    }
}

// ---- Launch ----
extern "C" void kernel_launch(void* const* d_in, const int* in_sizes, int n_in,
                              void* d_out, int out_size) {
    const float* x        = (const float*)d_in[0];
    const int*   experts  = (const int*)d_in[1];
    const float* norm1_w  = (const float*)d_in[2];
    const float* tdl      = (const float*)d_in[3];
    const float* norm2_w  = (const float*)d_in[4];
    const float* W        = (const float*)d_in[5];
    float* out = (float*)d_out;

    const int B = in_sizes[1];
    const int S = in_sizes[0] / (B * D);
    const int E = in_sizes[5] / (D * D);

    prep_kernel<<<1, 1024>>>(tdl, experts, B, E, S);

    dim3 gscan(NBX, B);
    scan_kernel<<<gscan, 256>>>(x, norm1_w, norm2_w, S);

    dim3 ggemm(D / 16, E, (B + GRP - 1) / GRP);
    gemm_kernel<<<ggemm, 256>>>(W, out);
}

// round 5
// speedup vs baseline: 1.7580x; 1.1100x over previous
#include <cuda_runtime.h>

#define D 1024
#define MAX_B 32
#define CHUNK 8
#define GRP 4
#define NBX 32
#define EPS 1e-6f

// 16-byte alignment REQUIRED: these are accessed as float4.
__device__ __align__(16) float g_state[MAX_B * D];   // zero at load; self-cleaning
__device__ __align__(16) float g_pool[MAX_B * D];
__device__ int g_arrive[MAX_B];                      // zero at load; self-cleaning

__device__ __forceinline__ float warp_sum(float v) {
#pragma unroll
    for (int o = 16; o > 0; o >>= 1) v += __shfl_xor_sync(0xffffffffu, v, o);
    return v;
}

// ---- Kernel 1: fused decay + truncated weighted scan + pool rmsnorm ----
__global__ void scan_kernel(const float* __restrict__ x,
                            const float* __restrict__ logit,
                            const float* __restrict__ norm1_w,
                            const float* __restrict__ norm2_w, int S) {
    const int b = blockIdx.y;
    const int tid = threadIdx.x;    // 256
    const int d0 = tid * 4;
    const int wid = tid >> 5, lane = tid & 31;

    // decay slice (computed per block; avoids a separate prep kernel)
    const float4 lg = *(const float4*)&logit[d0];
    float4 dc4;
    dc4.x = 1.f / (1.f + __expf(-lg.x));
    dc4.y = 1.f / (1.f + __expf(-lg.y));
    dc4.z = 1.f / (1.f + __expf(-lg.z));
    dc4.w = 1.f / (1.f + __expf(-lg.w));

    // block max(decay) -> nchunks (runtime truncation bound)
    __shared__ float smax[8];
    float m = fmaxf(fmaxf(dc4.x, dc4.y), fmaxf(dc4.z, dc4.w));
#pragma unroll
    for (int o = 16; o > 0; o >>= 1) m = fmaxf(m, __shfl_xor_sync(0xffffffffu, m, o));
    if (lane == 0) smax[wid] = m;
    __syncthreads();
    float maxd = fmaxf(fmaxf(smax[0], smax[1]), fmaxf(smax[2], smax[3]));
    maxd = fmaxf(maxd, fmaxf(fmaxf(smax[4], smax[5]), fmaxf(smax[6], smax[7])));

    const int sch = (S + CHUNK - 1) / CHUNK;
    int nch;
    if (maxd >= 0.9999995f) {
        nch = sch;
    } else {
        float K = logf(1e-12f) / logf(maxd);
        int Ki = (int)K + 2;
        nch = (Ki + CHUNK - 1) / CHUNK;
        if (nch > sch) nch = sch;
        if (nch < 1) nch = 1;
    }

    float4 acc = make_float4(0.f, 0.f, 0.f, 0.f);
    bool did = false;

    __shared__ float sred[CHUNK][8];
    __shared__ float srstd[CHUNK];

    for (int c = blockIdx.x; c < nch; c += NBX) {
        did = true;
        const int t_hi = S - 1 - c * CHUNK;
        int t_lo = t_hi - (CHUNK - 1);
        if (t_lo < 0) t_lo = 0;
        const int valid = t_hi - t_lo + 1;
        const int e_min = c * CHUNK;

        const float* xb = x + ((size_t)b * S + t_hi) * D + d0;
        float4 xr[CHUNK];
#pragma unroll
        for (int i = 0; i < CHUNK; i++) {
            if (i < valid) xr[i] = *(const float4*)(xb - (size_t)i * D);
            else           xr[i] = make_float4(0.f, 0.f, 0.f, 0.f);
        }

#pragma unroll
        for (int i = 0; i < CHUNK; i++) {
            float4 v = xr[i];
            float s = warp_sum(v.x * v.x + v.y * v.y + v.z * v.z + v.w * v.w);
            if (lane == 0) sred[i][wid] = s;
        }
        __syncthreads();
        if (tid < CHUNK) {
            float s = 0.f;
#pragma unroll
            for (int w = 0; w < 8; w++) s += sred[tid][w];
            srstd[tid] = rsqrtf(s * (1.f / D) + EPS);
        }
        __syncthreads();

        float4 w4;
        w4.x = __powf(dc4.x, (float)e_min);
        w4.y = __powf(dc4.y, (float)e_min);
        w4.z = __powf(dc4.z, (float)e_min);
        w4.w = __powf(dc4.w, (float)e_min);

#pragma unroll
        for (int i = 0; i < CHUNK; i++) {
            if (i < valid) {
                float r = srstd[i];
                acc.x += w4.x * xr[i].x * r;
                acc.y += w4.y * xr[i].y * r;
                acc.z += w4.z * xr[i].z * r;
                acc.w += w4.w * xr[i].w * r;
            }
            w4.x *= dc4.x; w4.y *= dc4.y; w4.z *= dc4.z; w4.w *= dc4.w;
        }
        __syncthreads();   // sred reuse
    }

    float* gs = &g_state[b * D + d0];
    if (did) {
        const float4 nw = *(const float4*)&norm1_w[d0];
        atomicAdd(gs + 0, acc.x * nw.x * (1.f - dc4.x));
        atomicAdd(gs + 1, acc.y * nw.y * (1.f - dc4.y));
        atomicAdd(gs + 2, acc.z * nw.z * (1.f - dc4.z));
        atomicAdd(gs + 3, acc.w * nw.w * (1.f - dc4.w));
    }

    // ---- last block per batch: pool rmsnorm + self-clean ----
    __threadfence();
    __shared__ int s_last;
    if (tid == 0)
        s_last = (atomicAdd(&g_arrive[b], 1) == NBX - 1);
    __syncthreads();
    if (!s_last) return;

    const float4 xl = *(const float4*)(x + ((size_t)b * S + (S - 1)) * D + d0);
    const float4 st = __ldcg((const float4*)gs);
    float4 v = make_float4(xl.x + st.x, xl.y + st.y, xl.z + st.z, xl.w + st.w);

    // reset for next graph replay
    *(float4*)gs = make_float4(0.f, 0.f, 0.f, 0.f);
    if (tid == 0) g_arrive[b] = 0;

    float s = warp_sum(v.x * v.x + v.y * v.y + v.z * v.z + v.w * v.w);
    __shared__ float sm2[8];
    __shared__ float srs;
    if (lane == 0) sm2[wid] = s;
    __syncthreads();
    if (tid == 0) {
        float t = 0.f;
#pragma unroll
        for (int w = 0; w < 8; w++) t += sm2[w];
        srs = rsqrtf(t * (1.f / D) + EPS);
    }
    __syncthreads();

    const float r = srs;
    const float4 n2 = *(const float4*)&norm2_w[d0];
    float4 p = make_float4(v.x * r * n2.x, v.y * r * n2.y,
                           v.z * r * n2.z, v.w * r * n2.w);
    *(float4*)&g_pool[b * D + d0] = p;
}

// ---- Kernel 2: expert-grouped GEMV, grouping computed in-block from smem ----
__global__ void gemm_kernel(const int* __restrict__ experts,
                            const float* __restrict__ W,
                            float* __restrict__ out, int B) {
    const int e = blockIdx.y;
    const int g = blockIdx.z;
    const int tid = threadIdx.x;   // 256

    __shared__ int s_exp[MAX_B];
    __shared__ int s_bl[MAX_B];
    __shared__ int s_nb;
    if (tid < B) s_exp[tid] = experts[tid];
    __syncthreads();
    if (tid == 0) {
        int n = 0;
        for (int b = 0; b < B; b++)
            if (s_exp[b] == e) s_bl[n++] = b;
        s_nb = n;
    }
    __syncthreads();

    const int nb = s_nb;
    const int base = g * GRP;
    if (base >= nb) return;
    const int cnt = min(GRP, nb - base);

    __shared__ __align__(16) float s_pool[GRP][D];   // 16 KB
#pragma unroll
    for (int j = 0; j < GRP; j++) {
        float4 p = make_float4(0.f, 0.f, 0.f, 0.f);
        if (j < cnt) p = *(const float4*)&g_pool[s_bl[base + j] * D + tid * 4];
        *(float4*)&s_pool[j][tid * 4] = p;
    }
    __syncthreads();

    const int warp = tid >> 5, lane = tid & 31;
    const int row0 = blockIdx.x * 16 + warp * 2;
    const float* W0 = W + ((size_t)e * D + row0) * D;
    const float* W1 = W0 + D;

    float acc0[GRP] = {0.f, 0.f, 0.f, 0.f};
    float acc1[GRP] = {0.f, 0.f, 0.f, 0.f};

    float4 a0 = __ldg((const float4*)(W0 + lane * 4));
    float4 a1 = __ldg((const float4*)(W1 + lane * 4));

#pragma unroll
    for (int i = 0; i < 8; i++) {
        float4 n0, n1;
        if (i < 7) {
            n0 = __ldg((const float4*)(W0 + (i + 1) * 128 + lane * 4));
            n1 = __ldg((const float4*)(W1 + (i + 1) * 128 + lane * 4));
        }
#pragma unroll
        for (int j = 0; j < GRP; j++) {
            const float4 p = *(const float4*)&s_pool[j][i * 128 + lane * 4];
            acc0[j] += a0.x * p.x + a0.y * p.y + a0.z * p.z + a0.w * p.w;
            acc1[j] += a1.x * p.x + a1.y * p.y + a1.z * p.z + a1.w * p.w;
        }
        if (i < 7) { a0 = n0; a1 = n1; }
    }

#pragma unroll
    for (int j = 0; j < GRP; j++) {
        float s0 = warp_sum(acc0[j]);
        float s1 = warp_sum(acc1[j]);
        if (lane == 0 && j < cnt) {
            const int ob = s_bl[base + j] * D;
            out[ob + row0]     = fmaxf(s0, 0.f);
            out[ob + row0 + 1] = fmaxf(s1, 0.f);
        }
    }
}

// ---- Launch ----
extern "C" void kernel_launch(void* const* d_in, const int* in_sizes, int n_in,
                              void* d_out, int out_size) {
    const float* x        = (const float*)d_in[0];
    const int*   experts  = (const int*)d_in[1];
    const float* norm1_w  = (const float*)d_in[2];
    const float* tdl      = (const float*)d_in[3];
    const float* norm2_w  = (const float*)d_in[4];
    const float* W        = (const float*)d_in[5];
    float* out = (float*)d_out;

    const int B = in_sizes[1];
    const int S = in_sizes[0] / (B * D);
    const int E = in_sizes[5] / (D * D);

    dim3 gscan(NBX, B);
    scan_kernel<<<gscan, 256>>>(x, tdl, norm1_w, norm2_w, S);

    dim3 ggemm(D / 16, E, (B + GRP - 1) / GRP);
    gemm_kernel<<<ggemm, 256>>>(experts, W, out, B);
}